// round 1
// baseline (speedup 1.0000x reference)
#include <cuda_runtime.h>
#include <math.h>

// Problem constants (fixed by setup_inputs)
#define B_ 4
#define S_ 8192
#define D_ 1024
#define H_ 1024
#define O_ 1024

#define SPART 8
#define SCHUNK (S_ / SPART)   // 1024 s per partition
#define BM 64                 // s-rows per tile
#define BN 64                 // j-cols per tile
#define BK 32                 // k per tile
#define NT 256                // threads per block
#define PADW 68               // padded row length (floats) for transposed tiles

// Scratch (no allocations allowed)
__device__ float g_pacc[B_][SPART][H_];   // partial sums of exp(diff)*g(h)
__device__ float g_dlast[B_][H_];         // diff at s = S-1
__device__ float g_hT[B_][H_];            // final hidden state

__device__ __forceinline__ float softplus_f(float x) {
    // log(1+exp(x)), stable: max(x,0) + log(1+exp(-|x|))
    float e = __expf(-fabsf(x));
    return fmaxf(x, 0.0f) + __logf(1.0f + e);
}

// ---------------------------------------------------------------------------
// Kernel 1: fused GEMM (z = x @ w_in^T for f,i,h gates) + elementwise +
// reduction over s.  Grid: (H/BN, SPART, B). Block: 256 threads.
// Each thread owns a 4(s) x 4(j) microtile for each of the 3 gates.
// ---------------------------------------------------------------------------
__global__ __launch_bounds__(NT) void k1_gemm_reduce(
    const float* __restrict__ x, const float* __restrict__ w_in)
{
    __shared__ float xsT[BK][PADW];
    __shared__ float wfT[BK][PADW];
    __shared__ float wiT[BK][PADW];
    __shared__ float whT[BK][PADW];
    __shared__ float sred[16][BN];

    const int jb  = blockIdx.x;   // 0..15
    const int sp  = blockIdx.y;   // 0..7
    const int b   = blockIdx.z;   // 0..3
    const int tid = threadIdx.x;
    const int tx  = tid & 15;     // j group  (4 cols each)
    const int ty  = tid >> 4;     // s group  (4 rows each)

    const int j0 = jb * BN;
    const float* xb = x    + ((size_t)b * S_ + (size_t)sp * SCHUNK) * D_;
    const float* wf = w_in + (size_t)(0 * H_ + j0) * D_;
    const float* wi = w_in + (size_t)(1 * H_ + j0) * D_;
    const float* wh = w_in + (size_t)(2 * H_ + j0) * D_;

    float accJ[4] = {0.f, 0.f, 0.f, 0.f};

    for (int st = 0; st < SCHUNK / BM; ++st) {
        float cf[4][4], ci[4][4], ch[4][4];
        #pragma unroll
        for (int m = 0; m < 4; ++m)
            #pragma unroll
            for (int n = 0; n < 4; ++n) { cf[m][n] = 0.f; ci[m][n] = 0.f; ch[m][n] = 0.f; }

        const float* xt = xb + (size_t)st * BM * D_;

        for (int kt = 0; kt < D_; kt += BK) {
            __syncthreads();
            // Load 64x32 tiles, store transposed [k][row] for vectorized reads.
            #pragma unroll
            for (int it = 0; it < 2; ++it) {
                int idx = tid + it * NT;      // 0..511
                int r   = idx >> 3;           // row 0..63
                int c4  = (idx & 7) * 4;      // col 0,4,...,28
                float4 xv = *(const float4*)(xt + (size_t)r * D_ + kt + c4);
                xsT[c4+0][r] = xv.x; xsT[c4+1][r] = xv.y;
                xsT[c4+2][r] = xv.z; xsT[c4+3][r] = xv.w;
                float4 fv = *(const float4*)(wf + (size_t)r * D_ + kt + c4);
                wfT[c4+0][r] = fv.x; wfT[c4+1][r] = fv.y;
                wfT[c4+2][r] = fv.z; wfT[c4+3][r] = fv.w;
                float4 iv = *(const float4*)(wi + (size_t)r * D_ + kt + c4);
                wiT[c4+0][r] = iv.x; wiT[c4+1][r] = iv.y;
                wiT[c4+2][r] = iv.z; wiT[c4+3][r] = iv.w;
                float4 hv = *(const float4*)(wh + (size_t)r * D_ + kt + c4);
                whT[c4+0][r] = hv.x; whT[c4+1][r] = hv.y;
                whT[c4+2][r] = hv.z; whT[c4+3][r] = hv.w;
            }
            __syncthreads();

            #pragma unroll 8
            for (int kk = 0; kk < BK; ++kk) {
                float4 xv = *(const float4*)&xsT[kk][ty * 4];
                float4 fv = *(const float4*)&wfT[kk][tx * 4];
                float4 iv = *(const float4*)&wiT[kk][tx * 4];
                float4 hv = *(const float4*)&whT[kk][tx * 4];
                float xm[4] = {xv.x, xv.y, xv.z, xv.w};
                float fn[4] = {fv.x, fv.y, fv.z, fv.w};
                float in[4] = {iv.x, iv.y, iv.z, iv.w};
                float hn[4] = {hv.x, hv.y, hv.z, hv.w};
                #pragma unroll
                for (int m = 0; m < 4; ++m)
                    #pragma unroll
                    for (int n = 0; n < 4; ++n) {
                        cf[m][n] = fmaf(xm[m], fn[n], cf[m][n]);
                        ci[m][n] = fmaf(xm[m], in[n], ci[m][n]);
                        ch[m][n] = fmaf(xm[m], hn[n], ch[m][n]);
                    }
            }
        }

        // Elementwise epilogue for this s-tile, reduce over s into accJ.
        const int sbase = sp * SCHUNK + st * BM + ty * 4;
        #pragma unroll
        for (int m = 0; m < 4; ++m) {
            int sg = sbase + m;
            #pragma unroll
            for (int n = 0; n < 4; ++n) {
                float f  = cf[m][n];
                float i_ = ci[m][n];
                float h  = ch[m][n];
                float diff = softplus_f(-f) - softplus_f(-i_);
                float gv = (h >= 0.0f) ? (h + 0.5f)
                                       : (1.0f / (1.0f + __expf(-h)));
                accJ[n] += __expf(diff) * gv;
                if (sg == S_ - 1) {
                    g_dlast[b][j0 + tx * 4 + n] = diff;
                }
            }
        }
    }

    // Reduce accJ across the 16 ty rows (same j columns).
    __syncthreads();
    #pragma unroll
    for (int n = 0; n < 4; ++n) sred[ty][tx * 4 + n] = accJ[n];
    __syncthreads();
    if (tid < BN) {
        float s = 0.f;
        #pragma unroll
        for (int r = 0; r < 16; ++r) s += sred[r][tid];
        g_pacc[b][sp][j0 + tid] = s;
    }
}

// ---------------------------------------------------------------------------
// Kernel 2: combine partitions -> h_T
// ---------------------------------------------------------------------------
__global__ void k2_combine()
{
    int b = blockIdx.x;
    int j = threadIdx.x;   // blockDim = 1024
    float s = 0.f;
    #pragma unroll
    for (int sp = 0; sp < SPART; ++sp) s += g_pacc[b][sp][j];
    float d = g_dlast[b][j];
    float sig = 1.0f / (1.0f + expf(d));   // exp(log_f[S-1]) = sigmoid(-diff)
    g_hT[b][j] = sig * (0.5f + s);
}

// ---------------------------------------------------------------------------
// Kernel 3: out = h_T @ w_out^T + b_out   (4 x 1024 x 1024, trivial)
// ---------------------------------------------------------------------------
__global__ __launch_bounds__(256) void k3_out(
    const float* __restrict__ w_out, const float* __restrict__ b_out,
    float* __restrict__ out)
{
    int b = blockIdx.y;
    int o = blockIdx.x * 256 + threadIdx.x;

    __shared__ float hs[H_];
    for (int j = threadIdx.x; j < H_; j += 256) hs[j] = g_hT[b][j];
    __syncthreads();

    float acc = b_out[o];
    const float4* wr = (const float4*)(w_out + (size_t)o * H_);
    #pragma unroll 4
    for (int q = 0; q < H_ / 4; ++q) {
        float4 w4 = wr[q];
        float4 h4 = *(const float4*)&hs[q * 4];
        acc = fmaf(w4.x, h4.x, acc);
        acc = fmaf(w4.y, h4.y, acc);
        acc = fmaf(w4.z, h4.z, acc);
        acc = fmaf(w4.w, h4.w, acc);
    }
    out[(size_t)b * O_ + o] = acc;
}

extern "C" void kernel_launch(void* const* d_in, const int* in_sizes, int n_in,
                              void* d_out, int out_size)
{
    (void)in_sizes; (void)n_in; (void)out_size;
    const float* x     = (const float*)d_in[0];   // [4, 8192, 1024]
    const float* w_in  = (const float*)d_in[1];   // [3072, 1024]
    const float* w_out = (const float*)d_in[2];   // [1024, 1024]
    const float* b_out = (const float*)d_in[3];   // [1024]
    float* out = (float*)d_out;                   // [4, 1024]

    dim3 g1(H_ / BN, SPART, B_);
    k1_gemm_reduce<<<g1, NT>>>(x, w_in);
    k2_combine<<<B_, 1024>>>();
    dim3 g3(O_ / 256, B_);
    k3_out<<<g3, 256>>>(w_out, b_out, out);
}

// round 4
// speedup vs baseline: 1.9528x; 1.9528x over previous
#include <cuda_runtime.h>
#include <cuda_bf16.h>
#include <cstdint>
#include <math.h>

// ---------------------------------------------------------------- constants
#define B_ 4
#define S_ 8192
#define D_ 1024
#define H_ 1024
#define O_ 1024

#define BM 128                 // s-rows per CTA tile
#define BN 64                  // j-cols per CTA tile (per gate; 3 gates)
#define BK 32                  // k per pipeline chunk
#define NCHUNK (D_ / BK)       // 32
#define NTH 256                // 8 warps

#define ROWB 80                // padded smem row stride bytes (64 data + 16)
#define A_TILE (BM * ROWB)     // 10240
#define B_TILE (BN * ROWB)     // 5120
#define B_OFF  (2 * A_TILE)    // after A hi+lo
#define STAGE  (2 * A_TILE + 6 * B_TILE)   // 51200
#define SMEM_DYN (2 * STAGE)               // 102400

#define MTILES (B_ * S_ / BM)  // 256
#define JTILES (H_ / BN)       // 16
#define MT_PER_B (S_ / BM)     // 64

// ---------------------------------------------------------------- scratch
__device__ __nv_bfloat16 g_xhi[B_ * S_ * D_];
__device__ __nv_bfloat16 g_xlo[B_ * S_ * D_];
__device__ __nv_bfloat16 g_whi[3 * H_ * D_];
__device__ __nv_bfloat16 g_wlo[3 * H_ * D_];
__device__ float g_pacc[B_][MT_PER_B][H_];
__device__ float g_sig[B_][H_];
__device__ float g_hT[B_][H_];

// ---------------------------------------------------------------- helpers
__device__ __forceinline__ uint32_t smem_u32(const void* p) {
    uint32_t a;
    asm("{ .reg .u64 t; cvta.to.shared.u64 t, %1; cvt.u32.u64 %0, t; }"
        : "=r"(a) : "l"(p));
    return a;
}

__device__ __forceinline__ void cp_async16(uint32_t dst, const void* src) {
    size_t g = (size_t)__cvta_generic_to_global(src);
    asm volatile("cp.async.cg.shared.global [%0], [%1], 16;\n"
                 :: "r"(dst), "l"(g));
}

__device__ __forceinline__ void ldsm_x4(uint32_t* r, uint32_t addr) {
    asm volatile("ldmatrix.sync.aligned.m8n8.x4.shared.b16 {%0,%1,%2,%3}, [%4];"
                 : "=r"(r[0]), "=r"(r[1]), "=r"(r[2]), "=r"(r[3]) : "r"(addr));
}

__device__ __forceinline__ void ldsm_x2(uint32_t* r, uint32_t addr) {
    asm volatile("ldmatrix.sync.aligned.m8n8.x2.shared.b16 {%0,%1}, [%2];"
                 : "=r"(r[0]), "=r"(r[1]) : "r"(addr));
}

__device__ __forceinline__ void mma16816(float* c, const uint32_t* a,
                                         const uint32_t* b) {
    asm volatile(
        "mma.sync.aligned.m16n8k16.row.col.f32.bf16.bf16.f32 "
        "{%0,%1,%2,%3}, {%4,%5,%6,%7}, {%8,%9}, {%0,%1,%2,%3};"
        : "+f"(c[0]), "+f"(c[1]), "+f"(c[2]), "+f"(c[3])
        : "r"(a[0]), "r"(a[1]), "r"(a[2]), "r"(a[3]), "r"(b[0]), "r"(b[1]));
}

// ---------------------------------------------------------------- prep: fp32 -> bf16 hi/lo
__global__ __launch_bounds__(256) void k_split(const float* __restrict__ src,
                                               __nv_bfloat16* __restrict__ hi,
                                               __nv_bfloat16* __restrict__ lo,
                                               int n4) {
    int i = blockIdx.x * 256 + threadIdx.x;
    if (i >= n4) return;
    float4 v = ((const float4*)src)[i];
    float vv[4] = {v.x, v.y, v.z, v.w};
    unsigned short hb[4], lb[4];
#pragma unroll
    for (int q = 0; q < 4; ++q) {
        __nv_bfloat16 h = __float2bfloat16(vv[q]);
        float r = vv[q] - __bfloat162float(h);
        __nv_bfloat16 l = __float2bfloat16(r);
        hb[q] = __bfloat16_as_ushort(h);
        lb[q] = __bfloat16_as_ushort(l);
    }
    uint2 hp, lp;
    hp.x = (uint32_t)hb[0] | ((uint32_t)hb[1] << 16);
    hp.y = (uint32_t)hb[2] | ((uint32_t)hb[3] << 16);
    lp.x = (uint32_t)lb[0] | ((uint32_t)lb[1] << 16);
    lp.y = (uint32_t)lb[2] | ((uint32_t)lb[3] << 16);
    ((uint2*)hi)[i] = hp;
    ((uint2*)lo)[i] = lp;
}

// ---------------------------------------------------------------- stage loader
__device__ __forceinline__ void load_stage(uint32_t sb, int k0, size_t xrow0,
                                           int j0, int tid) {
    // A: 2 parts (hi/lo) x 128 rows x 4 chunks = 1024 chunks
    // B: 2 parts x 3 gates x 64 rows x 4 chunks = 1536 chunks
#pragma unroll
    for (int it = 0; it < 10; ++it) {
        int idx = tid + it * NTH;
        if (idx < 1024) {
            int part = idx >> 9;
            int rem = idx & 511;
            int r = rem >> 2, c = rem & 3;
            const __nv_bfloat16* base = part ? g_xlo : g_xhi;
            const void* src = base + xrow0 + (size_t)r * D_ + k0 + c * 8;
            cp_async16(sb + part * A_TILE + r * ROWB + c * 16, src);
        } else {
            int bidx = idx - 1024;
            int part = bidx / 768;
            int rem = bidx - part * 768;
            int g = rem >> 8;
            int rr = rem & 255;
            int r = rr >> 2, c = rr & 3;
            const __nv_bfloat16* base = part ? g_wlo : g_whi;
            const void* src = base + (size_t)(g * H_ + j0 + r) * D_ + k0 + c * 8;
            cp_async16(sb + B_OFF + (part * 3 + g) * B_TILE + r * ROWB + c * 16,
                       src);
        }
    }
    asm volatile("cp.async.commit_group;" ::: "memory");
}

// ---------------------------------------------------------------- main fused GEMM+reduce
extern __shared__ __align__(128) char dynsmem[];

__global__ __launch_bounds__(NTH, 1) void k1_mma(void) {
    __shared__ float jacc[2][BN];

    const int tid = threadIdx.x;
    const int wid = tid >> 5;
    const int lane = tid & 31;
    const int wm = wid >> 2;            // 0..1 (64 rows each)
    const int wn = wid & 3;             // 0..3 (16 cols each)
    const int jt = blockIdx.x;          // 0..15
    const int mt = blockIdx.y;          // 0..255
    const int b = mt >> 6;
    const int mtb = mt & 63;
    const int j0 = jt * BN;

    const uint32_t sb0 = smem_u32(dynsmem);
    const size_t xrow0 = (size_t)mt * BM * D_;

    float acc[3][4][2][4];
#pragma unroll
    for (int g = 0; g < 3; ++g)
#pragma unroll
        for (int mf = 0; mf < 4; ++mf)
#pragma unroll
            for (int nf = 0; nf < 2; ++nf)
#pragma unroll
                for (int q = 0; q < 4; ++q) acc[g][mf][nf][q] = 0.0f;

    load_stage(sb0, 0, xrow0, j0, tid);

    for (int ck = 0; ck < NCHUNK; ++ck) {
        if (ck + 1 < NCHUNK) {
            load_stage(sb0 + ((ck + 1) & 1) * STAGE, (ck + 1) * BK, xrow0, j0,
                       tid);
            asm volatile("cp.async.wait_group 1;" ::: "memory");
        } else {
            asm volatile("cp.async.wait_group 0;" ::: "memory");
        }
        __syncthreads();

        const uint32_t sb = sb0 + (ck & 1) * STAGE;
        const uint32_t a_rowsel = (wm * 64 + (lane & 15)) * ROWB +
                                  ((lane >> 4) << 4);
        const uint32_t b_rowsel = (wn * 16 + (lane & 7)) * ROWB +
                                  (((lane >> 3) & 1) << 4);

#pragma unroll
        for (int ks = 0; ks < 2; ++ks) {
            const uint32_t koff = ks * 32;
            uint32_t ah[4][4], al[4][4];
#pragma unroll
            for (int mf = 0; mf < 4; ++mf) {
                uint32_t addr = sb + a_rowsel + mf * (16 * ROWB) + koff;
                ldsm_x4(ah[mf], addr);
                ldsm_x4(al[mf], addr + A_TILE);
            }
#pragma unroll
            for (int g = 0; g < 3; ++g) {
                uint32_t bh[2][2], bl[2][2];
#pragma unroll
                for (int nf = 0; nf < 2; ++nf) {
                    uint32_t addr = sb + B_OFF + g * B_TILE + b_rowsel +
                                    nf * (8 * ROWB) + koff;
                    ldsm_x2(bh[nf], addr);
                    ldsm_x2(bl[nf], addr + 3 * B_TILE);
                }
#pragma unroll
                for (int mf = 0; mf < 4; ++mf)
#pragma unroll
                    for (int nf = 0; nf < 2; ++nf)
                        mma16816(acc[g][mf][nf], ah[mf], bh[nf]);
#pragma unroll
                for (int mf = 0; mf < 4; ++mf)
#pragma unroll
                    for (int nf = 0; nf < 2; ++nf)
                        mma16816(acc[g][mf][nf], al[mf], bh[nf]);
#pragma unroll
                for (int mf = 0; mf < 4; ++mf)
#pragma unroll
                    for (int nf = 0; nf < 2; ++nf)
                        mma16816(acc[g][mf][nf], ah[mf], bl[nf]);
            }
        }
        __syncthreads();
    }

    // ---- epilogue: elementwise + reduce over s rows
    float vloc[2][2] = {{0.f, 0.f}, {0.f, 0.f}};   // [nf][q&1]
#pragma unroll
    for (int mf = 0; mf < 4; ++mf)
#pragma unroll
        for (int nf = 0; nf < 2; ++nf)
#pragma unroll
            for (int q = 0; q < 4; ++q) {
                float zf = acc[0][mf][nf][q];
                float zi = acc[1][mf][nf][q];
                float zh = acc[2][mf][nf][q];
                float R = __fdividef(1.0f + __expf(-zf),
                                     1.0f + __expf(-zi));   // exp(diff)
                float gv = (zh >= 0.0f)
                               ? (zh + 0.5f)
                               : __fdividef(1.0f, 1.0f + __expf(-zh));
                vloc[nf][q & 1] += R * gv;
                int row = wm * 64 + mf * 16 + (lane >> 2) + ((q >> 1) << 3);
                // within-batch s index: global row & (S_-1)
                if (((mt * BM + row) & (S_ - 1)) == (S_ - 1)) {
                    int j = j0 + wn * 16 + nf * 8 + (lane & 3) * 2 + (q & 1);
                    g_sig[b][j] = __fdividef(1.0f, 1.0f + R);
                }
            }
#pragma unroll
    for (int nf = 0; nf < 2; ++nf)
#pragma unroll
        for (int q1 = 0; q1 < 2; ++q1) {
            float v = vloc[nf][q1];
            v += __shfl_xor_sync(0xffffffffu, v, 4);
            v += __shfl_xor_sync(0xffffffffu, v, 8);
            v += __shfl_xor_sync(0xffffffffu, v, 16);
            if (lane < 4) jacc[wm][wn * 16 + nf * 8 + lane * 2 + q1] = v;
        }
    __syncthreads();
    if (tid < BN)
        g_pacc[b][mtb][j0 + tid] = jacc[0][tid] + jacc[1][tid];
}

// ---------------------------------------------------------------- combine
__global__ void k2_combine(void) {
    int b = blockIdx.x;
    int j = threadIdx.x;
    float s = 0.0f;
#pragma unroll
    for (int mtb = 0; mtb < MT_PER_B; ++mtb) s += g_pacc[b][mtb][j];
    g_hT[b][j] = g_sig[b][j] * (0.5f + s);
}

// ---------------------------------------------------------------- out = hT @ w_out^T + b
__global__ __launch_bounds__(256) void k3_out(const float* __restrict__ w_out,
                                              const float* __restrict__ b_out,
                                              float* __restrict__ out) {
    int b = blockIdx.y;
    int o = blockIdx.x * 256 + threadIdx.x;

    __shared__ float hs[H_];
    for (int j = threadIdx.x; j < H_; j += 256) hs[j] = g_hT[b][j];
    __syncthreads();

    float acc = b_out[o];
    const float4* wr = (const float4*)(w_out + (size_t)o * H_);
#pragma unroll 4
    for (int q = 0; q < H_ / 4; ++q) {
        float4 w4 = wr[q];
        float4 h4 = *(const float4*)&hs[q * 4];
        acc = fmaf(w4.x, h4.x, acc);
        acc = fmaf(w4.y, h4.y, acc);
        acc = fmaf(w4.z, h4.z, acc);
        acc = fmaf(w4.w, h4.w, acc);
    }
    out[(size_t)b * O_ + o] = acc;
}

// ---------------------------------------------------------------- launch
extern "C" void kernel_launch(void* const* d_in, const int* in_sizes, int n_in,
                              void* d_out, int out_size) {
    (void)in_sizes; (void)n_in; (void)out_size;
    const float* x     = (const float*)d_in[0];   // [4, 8192, 1024]
    const float* w_in  = (const float*)d_in[1];   // [3072, 1024]
    const float* w_out = (const float*)d_in[2];   // [1024, 1024]
    const float* b_out = (const float*)d_in[3];   // [1024]
    float* out = (float*)d_out;                   // [4, 1024]

    static int smem_set = 0;
    if (!smem_set) {
        cudaFuncSetAttribute(k1_mma, cudaFuncAttributeMaxDynamicSharedMemorySize,
                             SMEM_DYN);
        smem_set = 1;
    }

    __nv_bfloat16 *xhi, *xlo, *whi, *wlo;
    cudaGetSymbolAddress((void**)&xhi, g_xhi);
    cudaGetSymbolAddress((void**)&xlo, g_xlo);
    cudaGetSymbolAddress((void**)&whi, g_whi);
    cudaGetSymbolAddress((void**)&wlo, g_wlo);

    int nx4 = B_ * S_ * D_ / 4;
    int nw4 = 3 * H_ * D_ / 4;
    k_split<<<(nx4 + 255) / 256, 256>>>(x, xhi, xlo, nx4);
    k_split<<<(nw4 + 255) / 256, 256>>>(w_in, whi, wlo, nw4);

    dim3 g1(JTILES, MTILES);
    k1_mma<<<g1, NTH, SMEM_DYN>>>();
    k2_combine<<<B_, H_>>>();
    dim3 g3(O_ / 256, B_);
    k3_out<<<g3, 256>>>(w_out, b_out, out);
}

// round 5
// speedup vs baseline: 3.9511x; 2.0233x over previous
#include <cuda_runtime.h>
#include <cuda_fp16.h>
#include <cstdint>
#include <math.h>

// ---------------------------------------------------------------- constants
#define B_ 4
#define S_ 8192
#define D_ 1024
#define H_ 1024
#define O_ 1024

#define BM 128                 // s-rows per CTA tile
#define BN 64                  // j-cols per CTA tile (per gate; 3 gates)
#define BK 32                  // k per pipeline chunk
#define NCHUNK (D_ / BK)       // 32
#define NSTAGE 3
#define NTH 256                // 8 warps

#define ROWB 80                // padded smem row stride bytes (64 data + 16)
#define A_TILE (BM * ROWB)     // 10240
#define B_TILE (BN * ROWB)     // 5120
#define B_OFF  (2 * A_TILE)    // after A hi+lo
#define STAGE  (2 * A_TILE + 3 * B_TILE)   // 35840
#define SMEM_DYN (NSTAGE * STAGE)          // 107520

#define MTILES (B_ * S_ / BM)  // 256
#define JTILES (H_ / BN)       // 16
#define MT_PER_B (S_ / BM)     // 64

// ---------------------------------------------------------------- scratch
__device__ __half g_xhi[B_ * S_ * D_];
__device__ __half g_xlo[B_ * S_ * D_];
__device__ __half g_wh[3 * H_ * D_];
__device__ float g_pacc[B_][MT_PER_B][H_];
__device__ float g_sig[B_][H_];
__device__ float g_hT[B_][H_];

// ---------------------------------------------------------------- helpers
__device__ __forceinline__ uint32_t smem_u32(const void* p) {
    uint32_t a;
    asm("{ .reg .u64 t; cvta.to.shared.u64 t, %1; cvt.u32.u64 %0, t; }"
        : "=r"(a) : "l"(p));
    return a;
}

__device__ __forceinline__ void cp_async16(uint32_t dst, const void* src) {
    size_t g = (size_t)__cvta_generic_to_global(src);
    asm volatile("cp.async.cg.shared.global [%0], [%1], 16;\n"
                 :: "r"(dst), "l"(g));
}

__device__ __forceinline__ void ldsm_x4(uint32_t* r, uint32_t addr) {
    asm volatile("ldmatrix.sync.aligned.m8n8.x4.shared.b16 {%0,%1,%2,%3}, [%4];"
                 : "=r"(r[0]), "=r"(r[1]), "=r"(r[2]), "=r"(r[3]) : "r"(addr));
}

__device__ __forceinline__ void mma16816(float* c, const uint32_t* a,
                                         uint32_t b0, uint32_t b1) {
    asm volatile(
        "mma.sync.aligned.m16n8k16.row.col.f32.f16.f16.f32 "
        "{%0,%1,%2,%3}, {%4,%5,%6,%7}, {%8,%9}, {%0,%1,%2,%3};"
        : "+f"(c[0]), "+f"(c[1]), "+f"(c[2]), "+f"(c[3])
        : "r"(a[0]), "r"(a[1]), "r"(a[2]), "r"(a[3]), "r"(b0), "r"(b1));
}

// ---------------------------------------------------------------- prep kernels
__global__ __launch_bounds__(256) void k_split_x(const float* __restrict__ src,
                                                 __half* __restrict__ hi,
                                                 __half* __restrict__ lo,
                                                 int n4) {
    int i = blockIdx.x * 256 + threadIdx.x;
    if (i >= n4) return;
    float4 v = ((const float4*)src)[i];
    float vv[4] = {v.x, v.y, v.z, v.w};
    unsigned short hb[4], lb[4];
#pragma unroll
    for (int q = 0; q < 4; ++q) {
        __half h = __float2half_rn(vv[q]);
        float r = vv[q] - __half2float(h);
        __half l = __float2half_rn(r);
        hb[q] = __half_as_ushort(h);
        lb[q] = __half_as_ushort(l);
    }
    uint2 hp, lp;
    hp.x = (uint32_t)hb[0] | ((uint32_t)hb[1] << 16);
    hp.y = (uint32_t)hb[2] | ((uint32_t)hb[3] << 16);
    lp.x = (uint32_t)lb[0] | ((uint32_t)lb[1] << 16);
    lp.y = (uint32_t)lb[2] | ((uint32_t)lb[3] << 16);
    ((uint2*)hi)[i] = hp;
    ((uint2*)lo)[i] = lp;
}

__global__ __launch_bounds__(256) void k_split_w(const float* __restrict__ src,
                                                 __half* __restrict__ dst,
                                                 int n4) {
    int i = blockIdx.x * 256 + threadIdx.x;
    if (i >= n4) return;
    float4 v = ((const float4*)src)[i];
    unsigned short hb[4];
    hb[0] = __half_as_ushort(__float2half_rn(v.x));
    hb[1] = __half_as_ushort(__float2half_rn(v.y));
    hb[2] = __half_as_ushort(__float2half_rn(v.z));
    hb[3] = __half_as_ushort(__float2half_rn(v.w));
    uint2 hp;
    hp.x = (uint32_t)hb[0] | ((uint32_t)hb[1] << 16);
    hp.y = (uint32_t)hb[2] | ((uint32_t)hb[3] << 16);
    ((uint2*)dst)[i] = hp;
}

// ---------------------------------------------------------------- stage loader
__device__ __forceinline__ void load_stage(uint32_t sb, int k0, size_t xrow0,
                                           int j0, int tid) {
    // A: 2 parts (hi/lo) x 128 rows x 4 chunks = 1024
    // B: 3 gates x 64 rows x 4 chunks = 768 ; total 1792 = 7 * 256
#pragma unroll
    for (int it = 0; it < 7; ++it) {
        int idx = tid + it * NTH;
        if (idx < 1024) {
            int part = idx >> 9;
            int rem = idx & 511;
            int r = rem >> 2, c = rem & 3;
            const __half* base = part ? g_xlo : g_xhi;
            const void* src = base + xrow0 + (size_t)r * D_ + k0 + c * 8;
            cp_async16(sb + part * A_TILE + r * ROWB + c * 16, src);
        } else {
            int bidx = idx - 1024;
            int g = bidx >> 8;
            int rr = bidx & 255;
            int r = rr >> 2, c = rr & 3;
            const void* src = g_wh + (size_t)(g * H_ + j0 + r) * D_ + k0 + c * 8;
            cp_async16(sb + B_OFF + g * B_TILE + r * ROWB + c * 16, src);
        }
    }
    asm volatile("cp.async.commit_group;" ::: "memory");
}

// ---------------------------------------------------------------- main fused GEMM+reduce
extern __shared__ __align__(128) char dynsmem[];

__global__ __launch_bounds__(NTH, 1) void k1_mma(void) {
    __shared__ float jacc[2][BN];

    const int tid = threadIdx.x;
    const int wid = tid >> 5;
    const int lane = tid & 31;
    const int wm = wid >> 2;            // 0..1 (64 rows each)
    const int wn = wid & 3;             // 0..3 (16 cols each)
    const int jt = blockIdx.x;          // 0..15
    const int mt = blockIdx.y;          // 0..255
    const int b = mt >> 6;
    const int mtb = mt & 63;
    const int j0 = jt * BN;

    const uint32_t sb0 = smem_u32(dynsmem);
    const size_t xrow0 = (size_t)mt * BM * D_;

    float acc[3][4][2][4];
#pragma unroll
    for (int g = 0; g < 3; ++g)
#pragma unroll
        for (int mf = 0; mf < 4; ++mf)
#pragma unroll
            for (int nf = 0; nf < 2; ++nf)
#pragma unroll
                for (int q = 0; q < 4; ++q) acc[g][mf][nf][q] = 0.0f;

    load_stage(sb0 + 0 * STAGE, 0 * BK, xrow0, j0, tid);
    load_stage(sb0 + 1 * STAGE, 1 * BK, xrow0, j0, tid);

    const uint32_t a_rowsel = (wm * 64 + (lane & 15)) * ROWB +
                              ((lane >> 4) << 4);
    const uint32_t b_rowsel = (wn * 16 + (lane & 15)) * ROWB +
                              ((lane >> 4) << 4);

    for (int ck = 0; ck < NCHUNK; ++ck) {
        if (ck < NCHUNK - 1) {
            asm volatile("cp.async.wait_group 1;" ::: "memory");
        } else {
            asm volatile("cp.async.wait_group 0;" ::: "memory");
        }
        __syncthreads();

        // prefetch stage ck+2 into buffer (ck+2)%3 (read at iter ck-1; all
        // warps are past that read thanks to the barrier above)
        if (ck + 2 < NCHUNK) {
            load_stage(sb0 + ((ck + 2) % NSTAGE) * STAGE, (ck + 2) * BK, xrow0,
                       j0, tid);
        }

        const uint32_t sb = sb0 + (ck % NSTAGE) * STAGE;

#pragma unroll
        for (int ks = 0; ks < 2; ++ks) {
            const uint32_t koff = ks * 32;
            uint32_t ah[4][4], al[4][4];
#pragma unroll
            for (int mf = 0; mf < 4; ++mf) {
                uint32_t addr = sb + a_rowsel + mf * (16 * ROWB) + koff;
                ldsm_x4(ah[mf], addr);
                ldsm_x4(al[mf], addr + A_TILE);
            }
#pragma unroll
            for (int g = 0; g < 3; ++g) {
                uint32_t bq[4];   // r0=nf0.b0 r1=nf1.b0 r2=nf0.b1 r3=nf1.b1
                ldsm_x4(bq, sb + B_OFF + g * B_TILE + b_rowsel + koff);
#pragma unroll
                for (int mf = 0; mf < 4; ++mf) {
                    mma16816(acc[g][mf][0], ah[mf], bq[0], bq[2]);
                    mma16816(acc[g][mf][1], ah[mf], bq[1], bq[3]);
                }
#pragma unroll
                for (int mf = 0; mf < 4; ++mf) {
                    mma16816(acc[g][mf][0], al[mf], bq[0], bq[2]);
                    mma16816(acc[g][mf][1], al[mf], bq[1], bq[3]);
                }
            }
        }
    }

    // ---- epilogue: elementwise + reduce over s rows
    float vloc[2][2] = {{0.f, 0.f}, {0.f, 0.f}};   // [nf][q&1]
#pragma unroll
    for (int mf = 0; mf < 4; ++mf)
#pragma unroll
        for (int nf = 0; nf < 2; ++nf)
#pragma unroll
            for (int q = 0; q < 4; ++q) {
                float zf = acc[0][mf][nf][q];
                float zi = acc[1][mf][nf][q];
                float zh = acc[2][mf][nf][q];
                float R = __fdividef(1.0f + __expf(-zf),
                                     1.0f + __expf(-zi));   // exp(diff)
                float gv = (zh >= 0.0f)
                               ? (zh + 0.5f)
                               : __fdividef(1.0f, 1.0f + __expf(-zh));
                vloc[nf][q & 1] += R * gv;
                int row = wm * 64 + mf * 16 + (lane >> 2) + ((q >> 1) << 3);
                if (((mt * BM + row) & (S_ - 1)) == (S_ - 1)) {
                    int j = j0 + wn * 16 + nf * 8 + (lane & 3) * 2 + (q & 1);
                    g_sig[b][j] = __fdividef(1.0f, 1.0f + R);
                }
            }
#pragma unroll
    for (int nf = 0; nf < 2; ++nf)
#pragma unroll
        for (int q1 = 0; q1 < 2; ++q1) {
            float v = vloc[nf][q1];
            v += __shfl_xor_sync(0xffffffffu, v, 4);
            v += __shfl_xor_sync(0xffffffffu, v, 8);
            v += __shfl_xor_sync(0xffffffffu, v, 16);
            if (lane < 4) jacc[wm][wn * 16 + nf * 8 + lane * 2 + q1] = v;
        }
    __syncthreads();
    if (tid < BN)
        g_pacc[b][mtb][j0 + tid] = jacc[0][tid] + jacc[1][tid];
}

// ---------------------------------------------------------------- combine
__global__ void k2_combine(void) {
    int b = blockIdx.x;
    int j = threadIdx.x;
    float s = 0.0f;
#pragma unroll
    for (int mtb = 0; mtb < MT_PER_B; ++mtb) s += g_pacc[b][mtb][j];
    g_hT[b][j] = g_sig[b][j] * (0.5f + s);
}

// ---------------------------------------------------------------- out = hT @ w_out^T + b
__global__ __launch_bounds__(256) void k3_out(const float* __restrict__ w_out,
                                              const float* __restrict__ b_out,
                                              float* __restrict__ out) {
    int b = blockIdx.y;
    int o = blockIdx.x * 256 + threadIdx.x;

    __shared__ float hs[H_];
    for (int j = threadIdx.x; j < H_; j += 256) hs[j] = g_hT[b][j];
    __syncthreads();

    float acc = b_out[o];
    const float4* wr = (const float4*)(w_out + (size_t)o * H_);
#pragma unroll 4
    for (int q = 0; q < H_ / 4; ++q) {
        float4 w4 = wr[q];
        float4 h4 = *(const float4*)&hs[q * 4];
        acc = fmaf(w4.x, h4.x, acc);
        acc = fmaf(w4.y, h4.y, acc);
        acc = fmaf(w4.z, h4.z, acc);
        acc = fmaf(w4.w, h4.w, acc);
    }
    out[(size_t)b * O_ + o] = acc;
}

// ---------------------------------------------------------------- launch
extern "C" void kernel_launch(void* const* d_in, const int* in_sizes, int n_in,
                              void* d_out, int out_size) {
    (void)in_sizes; (void)n_in; (void)out_size;
    const float* x     = (const float*)d_in[0];   // [4, 8192, 1024]
    const float* w_in  = (const float*)d_in[1];   // [3072, 1024]
    const float* w_out = (const float*)d_in[2];   // [1024, 1024]
    const float* b_out = (const float*)d_in[3];   // [1024]
    float* out = (float*)d_out;                   // [4, 1024]

    static int smem_set = 0;
    if (!smem_set) {
        cudaFuncSetAttribute(k1_mma, cudaFuncAttributeMaxDynamicSharedMemorySize,
                             SMEM_DYN);
        smem_set = 1;
    }

    __half *xhi, *xlo, *wh;
    cudaGetSymbolAddress((void**)&xhi, g_xhi);
    cudaGetSymbolAddress((void**)&xlo, g_xlo);
    cudaGetSymbolAddress((void**)&wh, g_wh);

    int nx4 = B_ * S_ * D_ / 4;
    int nw4 = 3 * H_ * D_ / 4;
    k_split_x<<<(nx4 + 255) / 256, 256>>>(x, xhi, xlo, nx4);
    k_split_w<<<(nw4 + 255) / 256, 256>>>(w_in, wh, nw4);

    dim3 g1(JTILES, MTILES);
    k1_mma<<<g1, NTH, SMEM_DYN>>>();
    k2_combine<<<B_, H_>>>();
    dim3 g3(O_ / 256, B_);
    k3_out<<<g3, 256>>>(w_out, b_out, out);
}

// round 6
// speedup vs baseline: 6.3355x; 1.6035x over previous
#include <cuda_runtime.h>
#include <cuda_fp16.h>
#include <cstdint>
#include <math.h>

// ---------------------------------------------------------------- constants
#define B_ 4
#define S_ 8192
#define D_ 1024
#define H_ 1024
#define O_ 1024

#define BM 128                 // s-rows per CTA tile
#define BN 64                  // j-cols per CTA tile (per gate; 3 gates)
#define BK 32                  // k per pipeline chunk
#define NCHUNK (D_ / BK)       // 32
#define NSTAGE 4
#define NTH 256                // 8 warps

#define ROWB 80                // padded smem row stride bytes (64 data + 16)
#define A_TILE (BM * ROWB)     // 10240
#define B_TILE (BN * ROWB)     // 5120
#define B_OFF  A_TILE
#define STAGE  (A_TILE + 3 * B_TILE)       // 25600
#define SMEM_DYN (NSTAGE * STAGE)          // 102400

#define MTILES (B_ * S_ / BM)  // 256
#define JTILES (H_ / BN)       // 16
#define MT_PER_B (S_ / BM)     // 64

// ---------------------------------------------------------------- scratch
__device__ __half g_xh[B_ * S_ * D_];
__device__ __half g_wh[3 * H_ * D_];
__device__ float g_pacc[B_][MT_PER_B][H_];
__device__ float g_sig[B_][H_];
__device__ float g_hT[B_][H_];

// ---------------------------------------------------------------- helpers
__device__ __forceinline__ uint32_t smem_u32(const void* p) {
    uint32_t a;
    asm("{ .reg .u64 t; cvta.to.shared.u64 t, %1; cvt.u32.u64 %0, t; }"
        : "=r"(a) : "l"(p));
    return a;
}

__device__ __forceinline__ void cp_async16(uint32_t dst, const void* src) {
    size_t g = (size_t)__cvta_generic_to_global(src);
    asm volatile("cp.async.cg.shared.global [%0], [%1], 16;\n"
                 :: "r"(dst), "l"(g));
}

__device__ __forceinline__ void ldsm_x4(uint32_t* r, uint32_t addr) {
    asm volatile("ldmatrix.sync.aligned.m8n8.x4.shared.b16 {%0,%1,%2,%3}, [%4];"
                 : "=r"(r[0]), "=r"(r[1]), "=r"(r[2]), "=r"(r[3]) : "r"(addr));
}

__device__ __forceinline__ void mma16816(float* c, const uint32_t* a,
                                         uint32_t b0, uint32_t b1) {
    asm volatile(
        "mma.sync.aligned.m16n8k16.row.col.f32.f16.f16.f32 "
        "{%0,%1,%2,%3}, {%4,%5,%6,%7}, {%8,%9}, {%0,%1,%2,%3};"
        : "+f"(c[0]), "+f"(c[1]), "+f"(c[2]), "+f"(c[3])
        : "r"(a[0]), "r"(a[1]), "r"(a[2]), "r"(a[3]), "r"(b0), "r"(b1));
}

// ---------------------------------------------------------------- prep: fp32 -> fp16
__global__ __launch_bounds__(256) void k_cvt(const float* __restrict__ src,
                                             __half* __restrict__ dst,
                                             int n4) {
    int i = blockIdx.x * 256 + threadIdx.x;
    if (i >= n4) return;
    float4 v = ((const float4*)src)[i];
    unsigned short hb[4];
    hb[0] = __half_as_ushort(__float2half_rn(v.x));
    hb[1] = __half_as_ushort(__float2half_rn(v.y));
    hb[2] = __half_as_ushort(__float2half_rn(v.z));
    hb[3] = __half_as_ushort(__float2half_rn(v.w));
    uint2 hp;
    hp.x = (uint32_t)hb[0] | ((uint32_t)hb[1] << 16);
    hp.y = (uint32_t)hb[2] | ((uint32_t)hb[3] << 16);
    ((uint2*)dst)[i] = hp;
}

// ---------------------------------------------------------------- stage loader
__device__ __forceinline__ void load_stage(uint32_t sb, int k0, size_t xrow0,
                                           int j0, int tid) {
    // A: 128 rows x 4 chunks = 512 ; B: 3 gates x 64 rows x 4 = 768 ; 1280 total
#pragma unroll
    for (int it = 0; it < 5; ++it) {
        int idx = tid + it * NTH;
        if (idx < 512) {
            int r = idx >> 2, c = idx & 3;
            const void* src = g_xh + xrow0 + (size_t)r * D_ + k0 + c * 8;
            cp_async16(sb + r * ROWB + c * 16, src);
        } else {
            int bidx = idx - 512;
            int g = bidx >> 8;
            int rr = bidx & 255;
            int r = rr >> 2, c = rr & 3;
            const void* src = g_wh + (size_t)(g * H_ + j0 + r) * D_ + k0 + c * 8;
            cp_async16(sb + B_OFF + g * B_TILE + r * ROWB + c * 16, src);
        }
    }
    asm volatile("cp.async.commit_group;" ::: "memory");
}

// ---------------------------------------------------------------- main fused GEMM+reduce
extern __shared__ __align__(128) char dynsmem[];

__global__ __launch_bounds__(NTH, 1) void k1_mma(void) {
    __shared__ float jacc[2][BN];

    const int tid = threadIdx.x;
    const int wid = tid >> 5;
    const int lane = tid & 31;
    const int wm = wid >> 2;            // 0..1 (64 rows each)
    const int wn = wid & 3;             // 0..3 (16 cols each)
    const int jt = blockIdx.x;          // 0..15
    const int mt = blockIdx.y;          // 0..255
    const int b = mt >> 6;
    const int mtb = mt & 63;
    const int j0 = jt * BN;

    const uint32_t sb0 = smem_u32(dynsmem);
    const size_t xrow0 = (size_t)mt * BM * D_;

    float acc[3][4][2][4];
#pragma unroll
    for (int g = 0; g < 3; ++g)
#pragma unroll
        for (int mf = 0; mf < 4; ++mf)
#pragma unroll
            for (int nf = 0; nf < 2; ++nf)
#pragma unroll
                for (int q = 0; q < 4; ++q) acc[g][mf][nf][q] = 0.0f;

    load_stage(sb0 + 0 * STAGE, 0 * BK, xrow0, j0, tid);
    load_stage(sb0 + 1 * STAGE, 1 * BK, xrow0, j0, tid);
    load_stage(sb0 + 2 * STAGE, 2 * BK, xrow0, j0, tid);

    const uint32_t a_rowsel = (wm * 64 + (lane & 15)) * ROWB +
                              ((lane >> 4) << 4);
    const uint32_t b_rowsel = (wn * 16 + (lane & 15)) * ROWB +
                              ((lane >> 4) << 4);

    for (int ck = 0; ck < NCHUNK; ++ck) {
        if (ck <= NCHUNK - 3) {
            asm volatile("cp.async.wait_group 2;" ::: "memory");
        } else if (ck == NCHUNK - 2) {
            asm volatile("cp.async.wait_group 1;" ::: "memory");
        } else {
            asm volatile("cp.async.wait_group 0;" ::: "memory");
        }
        __syncthreads();

        // prefetch stage ck+3 into buffer (ck+3)%4 == (ck-1)%4; all warps are
        // past their reads of it thanks to the barrier above
        if (ck + 3 < NCHUNK) {
            load_stage(sb0 + ((ck + 3) % NSTAGE) * STAGE, (ck + 3) * BK, xrow0,
                       j0, tid);
        }

        const uint32_t sb = sb0 + (ck % NSTAGE) * STAGE;

#pragma unroll
        for (int ks = 0; ks < 2; ++ks) {
            const uint32_t koff = ks * 32;
            uint32_t ah[4][4];
#pragma unroll
            for (int mf = 0; mf < 4; ++mf)
                ldsm_x4(ah[mf], sb + a_rowsel + mf * (16 * ROWB) + koff);
#pragma unroll
            for (int g = 0; g < 3; ++g) {
                uint32_t bq[4];   // r0=nf0.b0 r1=nf1.b0 r2=nf0.b1 r3=nf1.b1
                ldsm_x4(bq, sb + B_OFF + g * B_TILE + b_rowsel + koff);
#pragma unroll
                for (int mf = 0; mf < 4; ++mf) {
                    mma16816(acc[g][mf][0], ah[mf], bq[0], bq[2]);
                    mma16816(acc[g][mf][1], ah[mf], bq[1], bq[3]);
                }
            }
        }
    }

    // ---- epilogue: elementwise + reduce over s rows
    float vloc[2][2] = {{0.f, 0.f}, {0.f, 0.f}};   // [nf][q&1]
#pragma unroll
    for (int mf = 0; mf < 4; ++mf)
#pragma unroll
        for (int nf = 0; nf < 2; ++nf)
#pragma unroll
            for (int q = 0; q < 4; ++q) {
                float zf = acc[0][mf][nf][q];
                float zi = acc[1][mf][nf][q];
                float zh = acc[2][mf][nf][q];
                float R = __fdividef(1.0f + __expf(-zf),
                                     1.0f + __expf(-zi));   // exp(diff)
                float gv = (zh >= 0.0f)
                               ? (zh + 0.5f)
                               : __fdividef(1.0f, 1.0f + __expf(-zh));
                vloc[nf][q & 1] += R * gv;
                int row = wm * 64 + mf * 16 + (lane >> 2) + ((q >> 1) << 3);
                if (((mt * BM + row) & (S_ - 1)) == (S_ - 1)) {
                    int j = j0 + wn * 16 + nf * 8 + (lane & 3) * 2 + (q & 1);
                    g_sig[b][j] = __fdividef(1.0f, 1.0f + R);
                }
            }
#pragma unroll
    for (int nf = 0; nf < 2; ++nf)
#pragma unroll
        for (int q1 = 0; q1 < 2; ++q1) {
            float v = vloc[nf][q1];
            v += __shfl_xor_sync(0xffffffffu, v, 4);
            v += __shfl_xor_sync(0xffffffffu, v, 8);
            v += __shfl_xor_sync(0xffffffffu, v, 16);
            if (lane < 4) jacc[wm][wn * 16 + nf * 8 + lane * 2 + q1] = v;
        }
    __syncthreads();
    if (tid < BN)
        g_pacc[b][mtb][j0 + tid] = jacc[0][tid] + jacc[1][tid];
}

// ---------------------------------------------------------------- combine
__global__ void k2_combine(void) {
    int b = blockIdx.x;
    int j = threadIdx.x;
    float s = 0.0f;
#pragma unroll
    for (int mtb = 0; mtb < MT_PER_B; ++mtb) s += g_pacc[b][mtb][j];
    g_hT[b][j] = g_sig[b][j] * (0.5f + s);
}

// ---------------------------------------------------------------- out = hT @ w_out^T + b
__global__ __launch_bounds__(256) void k3_out(const float* __restrict__ w_out,
                                              const float* __restrict__ b_out,
                                              float* __restrict__ out) {
    int b = blockIdx.y;
    int o = blockIdx.x * 256 + threadIdx.x;

    __shared__ float hs[H_];
    for (int j = threadIdx.x; j < H_; j += 256) hs[j] = g_hT[b][j];
    __syncthreads();

    float acc = b_out[o];
    const float4* wr = (const float4*)(w_out + (size_t)o * H_);
#pragma unroll 4
    for (int q = 0; q < H_ / 4; ++q) {
        float4 w4 = wr[q];
        float4 h4 = *(const float4*)&hs[q * 4];
        acc = fmaf(w4.x, h4.x, acc);
        acc = fmaf(w4.y, h4.y, acc);
        acc = fmaf(w4.z, h4.z, acc);
        acc = fmaf(w4.w, h4.w, acc);
    }
    out[(size_t)b * O_ + o] = acc;
}

// ---------------------------------------------------------------- launch
extern "C" void kernel_launch(void* const* d_in, const int* in_sizes, int n_in,
                              void* d_out, int out_size) {
    (void)in_sizes; (void)n_in; (void)out_size;
    const float* x     = (const float*)d_in[0];   // [4, 8192, 1024]
    const float* w_in  = (const float*)d_in[1];   // [3072, 1024]
    const float* w_out = (const float*)d_in[2];   // [1024, 1024]
    const float* b_out = (const float*)d_in[3];   // [1024]
    float* out = (float*)d_out;                   // [4, 1024]

    static int smem_set = 0;
    if (!smem_set) {
        cudaFuncSetAttribute(k1_mma, cudaFuncAttributeMaxDynamicSharedMemorySize,
                             SMEM_DYN);
        smem_set = 1;
    }

    __half *xh, *wh;
    cudaGetSymbolAddress((void**)&xh, g_xh);
    cudaGetSymbolAddress((void**)&wh, g_wh);

    int nx4 = B_ * S_ * D_ / 4;
    int nw4 = 3 * H_ * D_ / 4;
    k_cvt<<<(nx4 + 255) / 256, 256>>>(x, xh, nx4);
    k_cvt<<<(nw4 + 255) / 256, 256>>>(w_in, wh, nw4);

    dim3 g1(JTILES, MTILES);
    k1_mma<<<g1, NTH, SMEM_DYN>>>();
    k2_combine<<<B_, H_>>>();
    dim3 g3(O_ / 256, B_);
    k3_out<<<g3, 256>>>(w_out, b_out, out);
}

// round 7
// speedup vs baseline: 6.6037x; 1.0423x over previous
#include <cuda_runtime.h>
#include <cuda_fp16.h>
#include <cstdint>
#include <math.h>

// ---------------------------------------------------------------- constants
#define B_ 4
#define S_ 8192
#define D_ 1024
#define H_ 1024
#define O_ 1024

#define BM 128                 // s-rows per CTA tile
#define BN 64                  // j-cols per CTA tile (per gate; 3 gates)
#define BK 32                  // k per pipeline chunk
#define NCHUNK (D_ / BK)       // 32
#define NSTAGE 4
#define NTH 512                // 16 warps (4 per SMSP)

#define ROWB 80                // padded smem row stride bytes (64 data + 16)
#define A_TILE (BM * ROWB)     // 10240
#define B_TILE (BN * ROWB)     // 5120
#define B_OFF  A_TILE
#define STAGE  (A_TILE + 3 * B_TILE)       // 25600
#define SMEM_DYN (NSTAGE * STAGE)          // 102400

#define MTILES (B_ * S_ / BM)  // 256
#define JTILES (H_ / BN)       // 16
#define MT_PER_B (S_ / BM)     // 64

// ---------------------------------------------------------------- scratch
__device__ __half g_xh[B_ * S_ * D_];
__device__ __half g_wh[3 * H_ * D_];
__device__ float g_pacc[B_][MT_PER_B][H_];
__device__ float g_sig[B_][H_];
__device__ float g_hT[B_][H_];

// ---------------------------------------------------------------- helpers
__device__ __forceinline__ uint32_t smem_u32(const void* p) {
    uint32_t a;
    asm("{ .reg .u64 t; cvta.to.shared.u64 t, %1; cvt.u32.u64 %0, t; }"
        : "=r"(a) : "l"(p));
    return a;
}

__device__ __forceinline__ void cp_async16(uint32_t dst, const void* src) {
    size_t g = (size_t)__cvta_generic_to_global(src);
    asm volatile("cp.async.cg.shared.global [%0], [%1], 16;\n"
                 :: "r"(dst), "l"(g));
}

__device__ __forceinline__ void ldsm_x4(uint32_t* r, uint32_t addr) {
    asm volatile("ldmatrix.sync.aligned.m8n8.x4.shared.b16 {%0,%1,%2,%3}, [%4];"
                 : "=r"(r[0]), "=r"(r[1]), "=r"(r[2]), "=r"(r[3]) : "r"(addr));
}

__device__ __forceinline__ void mma16816(float* c, const uint32_t* a,
                                         uint32_t b0, uint32_t b1) {
    asm volatile(
        "mma.sync.aligned.m16n8k16.row.col.f32.f16.f16.f32 "
        "{%0,%1,%2,%3}, {%4,%5,%6,%7}, {%8,%9}, {%0,%1,%2,%3};"
        : "+f"(c[0]), "+f"(c[1]), "+f"(c[2]), "+f"(c[3])
        : "r"(a[0]), "r"(a[1]), "r"(a[2]), "r"(a[3]), "r"(b0), "r"(b1));
}

// ---------------------------------------------------------------- prep: fp32 -> fp16
__global__ __launch_bounds__(256) void k_cvt(const float* __restrict__ src,
                                             __half* __restrict__ dst,
                                             int n4) {
    int i = blockIdx.x * 256 + threadIdx.x;
    if (i >= n4) return;
    float4 v = ((const float4*)src)[i];
    unsigned short hb[4];
    hb[0] = __half_as_ushort(__float2half_rn(v.x));
    hb[1] = __half_as_ushort(__float2half_rn(v.y));
    hb[2] = __half_as_ushort(__float2half_rn(v.z));
    hb[3] = __half_as_ushort(__float2half_rn(v.w));
    uint2 hp;
    hp.x = (uint32_t)hb[0] | ((uint32_t)hb[1] << 16);
    hp.y = (uint32_t)hb[2] | ((uint32_t)hb[3] << 16);
    ((uint2*)dst)[i] = hp;
}

// ---------------------------------------------------------------- stage loader
__device__ __forceinline__ void load_stage(uint32_t sb, int k0, size_t xrow0,
                                           int j0, int tid) {
    // A: 128 rows x 4 chunks = 512 ; B: 3 gates x 64 rows x 4 = 768 ; 1280 total
#pragma unroll
    for (int it = 0; it < 3; ++it) {
        int idx = tid + it * NTH;
        if (it == 2 && idx >= 1280) break;
        if (idx < 512) {
            int r = idx >> 2, c = idx & 3;
            const void* src = g_xh + xrow0 + (size_t)r * D_ + k0 + c * 8;
            cp_async16(sb + r * ROWB + c * 16, src);
        } else {
            int bidx = idx - 512;
            int g = bidx >> 8;
            int rr = bidx & 255;
            int r = rr >> 2, c = rr & 3;
            const void* src = g_wh + (size_t)(g * H_ + j0 + r) * D_ + k0 + c * 8;
            cp_async16(sb + B_OFF + g * B_TILE + r * ROWB + c * 16, src);
        }
    }
    asm volatile("cp.async.commit_group;" ::: "memory");
}

// ---------------------------------------------------------------- main fused GEMM+reduce
extern __shared__ __align__(128) char dynsmem[];

__global__ __launch_bounds__(NTH, 1) void k1_mma(void) {
    __shared__ float jacc[4][BN];

    const int tid = threadIdx.x;
    const int wid = tid >> 5;
    const int lane = tid & 31;
    const int wm = wid >> 2;            // 0..3 (32 rows each)
    const int wn = wid & 3;             // 0..3 (16 cols each)
    const int jt = blockIdx.x;          // 0..15
    const int mt = blockIdx.y;          // 0..255
    const int b = mt >> 6;
    const int mtb = mt & 63;
    const int j0 = jt * BN;

    const uint32_t sb0 = smem_u32(dynsmem);
    const size_t xrow0 = (size_t)mt * BM * D_;

    float acc[3][2][2][4];
#pragma unroll
    for (int g = 0; g < 3; ++g)
#pragma unroll
        for (int mf = 0; mf < 2; ++mf)
#pragma unroll
            for (int nf = 0; nf < 2; ++nf)
#pragma unroll
                for (int q = 0; q < 4; ++q) acc[g][mf][nf][q] = 0.0f;

    load_stage(sb0 + 0 * STAGE, 0 * BK, xrow0, j0, tid);
    load_stage(sb0 + 1 * STAGE, 1 * BK, xrow0, j0, tid);
    load_stage(sb0 + 2 * STAGE, 2 * BK, xrow0, j0, tid);

    const uint32_t a_rowsel = (wm * 32 + (lane & 15)) * ROWB +
                              ((lane >> 4) << 4);
    const uint32_t b_rowsel = (wn * 16 + (lane & 15)) * ROWB +
                              ((lane >> 4) << 4);

    for (int ck = 0; ck < NCHUNK; ++ck) {
        if (ck <= NCHUNK - 3) {
            asm volatile("cp.async.wait_group 2;" ::: "memory");
        } else if (ck == NCHUNK - 2) {
            asm volatile("cp.async.wait_group 1;" ::: "memory");
        } else {
            asm volatile("cp.async.wait_group 0;" ::: "memory");
        }
        __syncthreads();

        // prefetch stage ck+3 into buffer (ck+3)%4 == (ck-1)%4; all warps are
        // past their reads of it thanks to the barrier above
        if (ck + 3 < NCHUNK) {
            load_stage(sb0 + ((ck + 3) % NSTAGE) * STAGE, (ck + 3) * BK, xrow0,
                       j0, tid);
        }

        const uint32_t sb = sb0 + (ck % NSTAGE) * STAGE;

#pragma unroll
        for (int ks = 0; ks < 2; ++ks) {
            const uint32_t koff = ks * 32;
            uint32_t ah[2][4];
#pragma unroll
            for (int mf = 0; mf < 2; ++mf)
                ldsm_x4(ah[mf], sb + a_rowsel + mf * (16 * ROWB) + koff);
#pragma unroll
            for (int g = 0; g < 3; ++g) {
                uint32_t bq[4];   // r0=nf0.b0 r1=nf1.b0 r2=nf0.b1 r3=nf1.b1
                ldsm_x4(bq, sb + B_OFF + g * B_TILE + b_rowsel + koff);
#pragma unroll
                for (int mf = 0; mf < 2; ++mf) {
                    mma16816(acc[g][mf][0], ah[mf], bq[0], bq[2]);
                    mma16816(acc[g][mf][1], ah[mf], bq[1], bq[3]);
                }
            }
        }
    }

    // ---- epilogue: elementwise + reduce over s rows
    float vloc[2][2] = {{0.f, 0.f}, {0.f, 0.f}};   // [nf][q&1]
#pragma unroll
    for (int mf = 0; mf < 2; ++mf)
#pragma unroll
        for (int nf = 0; nf < 2; ++nf)
#pragma unroll
            for (int q = 0; q < 4; ++q) {
                float zf = acc[0][mf][nf][q];
                float zi = acc[1][mf][nf][q];
                float zh = acc[2][mf][nf][q];
                float R = __fdividef(1.0f + __expf(-zf),
                                     1.0f + __expf(-zi));   // exp(diff)
                float gv = (zh >= 0.0f)
                               ? (zh + 0.5f)
                               : __fdividef(1.0f, 1.0f + __expf(-zh));
                vloc[nf][q & 1] += R * gv;
                int row = wm * 32 + mf * 16 + (lane >> 2) + ((q >> 1) << 3);
                if (((mt * BM + row) & (S_ - 1)) == (S_ - 1)) {
                    int j = j0 + wn * 16 + nf * 8 + (lane & 3) * 2 + (q & 1);
                    g_sig[b][j] = __fdividef(1.0f, 1.0f + R);
                }
            }
#pragma unroll
    for (int nf = 0; nf < 2; ++nf)
#pragma unroll
        for (int q1 = 0; q1 < 2; ++q1) {
            float v = vloc[nf][q1];
            v += __shfl_xor_sync(0xffffffffu, v, 4);
            v += __shfl_xor_sync(0xffffffffu, v, 8);
            v += __shfl_xor_sync(0xffffffffu, v, 16);
            if (lane < 4) jacc[wm][wn * 16 + nf * 8 + lane * 2 + q1] = v;
        }
    __syncthreads();
    if (tid < BN)
        g_pacc[b][mtb][j0 + tid] =
            jacc[0][tid] + jacc[1][tid] + jacc[2][tid] + jacc[3][tid];
}

// ---------------------------------------------------------------- combine
__global__ void k2_combine(void) {
    int b = blockIdx.x;
    int j = threadIdx.x;
    float s = 0.0f;
#pragma unroll
    for (int mtb = 0; mtb < MT_PER_B; ++mtb) s += g_pacc[b][mtb][j];
    g_hT[b][j] = g_sig[b][j] * (0.5f + s);
}

// ---------------------------------------------------------------- out = hT @ w_out^T + b
__global__ __launch_bounds__(256) void k3_out(const float* __restrict__ w_out,
                                              const float* __restrict__ b_out,
                                              float* __restrict__ out) {
    int b = blockIdx.y;
    int o = blockIdx.x * 256 + threadIdx.x;

    __shared__ float hs[H_];
    for (int j = threadIdx.x; j < H_; j += 256) hs[j] = g_hT[b][j];
    __syncthreads();

    float acc = b_out[o];
    const float4* wr = (const float4*)(w_out + (size_t)o * H_);
#pragma unroll 4
    for (int q = 0; q < H_ / 4; ++q) {
        float4 w4 = wr[q];
        float4 h4 = *(const float4*)&hs[q * 4];
        acc = fmaf(w4.x, h4.x, acc);
        acc = fmaf(w4.y, h4.y, acc);
        acc = fmaf(w4.z, h4.z, acc);
        acc = fmaf(w4.w, h4.w, acc);
    }
    out[(size_t)b * O_ + o] = acc;
}

// ---------------------------------------------------------------- launch
extern "C" void kernel_launch(void* const* d_in, const int* in_sizes, int n_in,
                              void* d_out, int out_size) {
    (void)in_sizes; (void)n_in; (void)out_size;
    const float* x     = (const float*)d_in[0];   // [4, 8192, 1024]
    const float* w_in  = (const float*)d_in[1];   // [3072, 1024]
    const float* w_out = (const float*)d_in[2];   // [1024, 1024]
    const float* b_out = (const float*)d_in[3];   // [1024]
    float* out = (float*)d_out;                   // [4, 1024]

    static int smem_set = 0;
    if (!smem_set) {
        cudaFuncSetAttribute(k1_mma, cudaFuncAttributeMaxDynamicSharedMemorySize,
                             SMEM_DYN);
        smem_set = 1;
    }

    __half *xh, *wh;
    cudaGetSymbolAddress((void**)&xh, g_xh);
    cudaGetSymbolAddress((void**)&wh, g_wh);

    int nx4 = B_ * S_ * D_ / 4;
    int nw4 = 3 * H_ * D_ / 4;
    k_cvt<<<(nx4 + 255) / 256, 256>>>(x, xh, nx4);
    k_cvt<<<(nw4 + 255) / 256, 256>>>(w_in, wh, nw4);

    dim3 g1(JTILES, MTILES);
    k1_mma<<<g1, NTH, SMEM_DYN>>>();
    k2_combine<<<B_, H_>>>();
    dim3 g3(O_ / 256, B_);
    k3_out<<<g3, 256>>>(w_out, b_out, out);
}